// round 4
// baseline (speedup 1.0000x reference)
#include <cuda_runtime.h>

#define B 32
#define S 1024
#define W 512
#define D 768
#define NPOS 32
#define NT 256          // 8 warps per CTA, one word per warp
#define NBLK ((B * W) / 8)   // 2048 CTAs -> exactly 16384 warps

__global__ void __launch_bounds__(NT) charpool_warp_kernel(
    const float* __restrict__ feats,      // [B, S, D]
    const int* __restrict__ word_lens,    // [B, W]
    const int* __restrict__ seq_len,      // [B]
    const int* __restrict__ pos,          // [B, W]
    const float* __restrict__ pos_table,  // [NPOS, D]
    float* __restrict__ out)              // [B, W, D]
{
    const int lane = threadIdx.x & 31;
    const int wpw  = threadIdx.x >> 5;
    const int id   = blockIdx.x * 8 + wpw;   // global word index, < B*W

    const int b = id >> 9;        // /W
    const int w = id & (W - 1);

    // lane-uniform metadata loads (broadcast)
    const int start = __ldg(&word_lens[id]);
    const int nxt   = (w + 1 < W) ? __ldg(&word_lens[id + 1]) : 0;
    const int p     = __ldg(&pos[id]);
    const int sl    = __ldg(&seq_len[b]);

    const int end   = (nxt == 0) ? sl : nxt;
    const bool valid = (start != 0) || (w == 0);

    float4 r[6];

    if (valid) {
        int len = end - start;
        if (len < 1) len = 1;

        const float4* fp = reinterpret_cast<const float4*>(
            feats + ((size_t)b * S + (size_t)start) * D);

        float4 acc[6];
        #pragma unroll
        for (int i = 0; i < 6; ++i) acc[i] = make_float4(0.f, 0.f, 0.f, 0.f);

        for (int s = 0; s < len; ++s) {
            // 6 independent 512B loads covering the full 3KB row (MLP=6)
            float4 v[6];
            #pragma unroll
            for (int i = 0; i < 6; ++i) v[i] = fp[i * 32 + lane];
            #pragma unroll
            for (int i = 0; i < 6; ++i) {
                acc[i].x += v[i].x; acc[i].y += v[i].y;
                acc[i].z += v[i].z; acc[i].w += v[i].w;
            }
            fp += D / 4;
        }

        // pos_table row (L2-hot) loaded after accumulation to cap live registers
        const float4* pt4 = reinterpret_cast<const float4*>(pos_table + (size_t)p * D);
        const float inv = 1.0f / (float)len;
        #pragma unroll
        for (int i = 0; i < 6; ++i) {
            const float4 pt = pt4[i * 32 + lane];
            r[i].x = fmaf(acc[i].x, inv, pt.x);
            r[i].y = fmaf(acc[i].y, inv, pt.y);
            r[i].z = fmaf(acc[i].z, inv, pt.z);
            r[i].w = fmaf(acc[i].w, inv, pt.w);
        }
    } else {
        // padding word: output = pos_table[pos]; pos=0 row is zero
        const float4* pt4 = reinterpret_cast<const float4*>(pos_table + (size_t)p * D);
        #pragma unroll
        for (int i = 0; i < 6; ++i) r[i] = pt4[i * 32 + lane];
    }

    float4* op = reinterpret_cast<float4*>(out + (size_t)id * D);
    #pragma unroll
    for (int i = 0; i < 6; ++i) op[i * 32 + lane] = r[i];
}

extern "C" void kernel_launch(void* const* d_in, const int* in_sizes, int n_in,
                              void* d_out, int out_size)
{
    const float* feats     = (const float*)d_in[0];
    const int*   word_lens = (const int*)d_in[1];
    const int*   seq_len   = (const int*)d_in[2];
    const int*   pos       = (const int*)d_in[3];
    const float* pos_table = (const float*)d_in[4];
    float* out = (float*)d_out;

    charpool_warp_kernel<<<NBLK, NT>>>(feats, word_lens, seq_len, pos, pos_table, out);
}

// round 5
// speedup vs baseline: 1.1429x; 1.1429x over previous
#include <cuda_runtime.h>

#define B 32
#define S 1024
#define W 512
#define D 768
#define NPOS 32
#define NT 192           // = D/4 threads, one float4 column per thread
#define TOTW (B * W)     // 16384 words
#define NBLK 1480        // ~single wave of persistent CTAs

__global__ void __launch_bounds__(NT) charpool_persist_kernel(
    const float* __restrict__ feats,      // [B, S, D]
    const int* __restrict__ word_lens,    // [B, W]
    const int* __restrict__ seq_len,      // [B]
    const int* __restrict__ pos,          // [B, W]
    const float* __restrict__ pos_table,  // [NPOS, D]
    float* __restrict__ out)              // [B, W, D]
{
    const int t = threadIdx.x;
    const float4* __restrict__ ptab = reinterpret_cast<const float4*>(pos_table);

    int id = blockIdx.x;
    if (id >= TOTW) return;

    // metadata for first word
    int start = __ldg(&word_lens[id]);
    int nxt   = ((id & (W - 1)) + 1 < W) ? __ldg(&word_lens[id + 1]) : 0;
    int p     = __ldg(&pos[id]);
    int sl    = __ldg(&seq_len[id >> 9]);

    for (;;) {
        // ---- prefetch next word's metadata (overlaps current feats latency) ----
        const int nid  = id + NBLK;
        const bool more = (nid < TOTW);
        int n_start = 0, n_nxt = 0, n_p = 0, n_sl = 0;
        if (more) {
            n_start = __ldg(&word_lens[nid]);
            n_nxt   = ((nid & (W - 1)) + 1 < W) ? __ldg(&word_lens[nid + 1]) : 0;
            n_p     = __ldg(&pos[nid]);
            n_sl    = __ldg(&seq_len[nid >> 9]);
        }

        // ---- process current word ----
        const int b   = id >> 9;
        const int w   = id & (W - 1);
        const int end = (nxt == 0) ? sl : nxt;
        const bool valid = (start != 0) || (w == 0);

        const float4 pt = ptab[p * (D / 4) + t];
        float4 r;

        if (valid) {
            int len = end - start;
            if (len < 1) len = 1;
            const float4* fp = reinterpret_cast<const float4*>(
                feats + ((size_t)b * S + (size_t)start) * D) + t;

            float4 acc = make_float4(0.f, 0.f, 0.f, 0.f);
            for (int s = 0; s < len; s += 4) {
                // issue up to 4 independent row loads before accumulating (MLP=4)
                float4 v0, v1, v2, v3;
                v0 = fp[0 * (D / 4)];
                v1 = (s + 1 < len) ? fp[1 * (D / 4)] : make_float4(0.f, 0.f, 0.f, 0.f);
                v2 = (s + 2 < len) ? fp[2 * (D / 4)] : make_float4(0.f, 0.f, 0.f, 0.f);
                v3 = (s + 3 < len) ? fp[3 * (D / 4)] : make_float4(0.f, 0.f, 0.f, 0.f);
                acc.x += (v0.x + v1.x) + (v2.x + v3.x);
                acc.y += (v0.y + v1.y) + (v2.y + v3.y);
                acc.z += (v0.z + v1.z) + (v2.z + v3.z);
                acc.w += (v0.w + v1.w) + (v2.w + v3.w);
                fp += 4 * (D / 4);
            }
            const float inv = 1.0f / (float)len;
            r.x = fmaf(acc.x, inv, pt.x);
            r.y = fmaf(acc.y, inv, pt.y);
            r.z = fmaf(acc.z, inv, pt.z);
            r.w = fmaf(acc.w, inv, pt.w);
        } else {
            r = pt;  // pos=0 row of the table is zero -> zeros for padding words
        }

        // streaming store: evict-first so the write stream doesn't thrash
        // L2-resident feats (out has zero reuse; feats is re-read every replay)
        __stcs(reinterpret_cast<float4*>(out + (size_t)id * D) + t, r);

        if (!more) break;
        id = nid;
        start = n_start; nxt = n_nxt; p = n_p; sl = n_sl;
    }
}

extern "C" void kernel_launch(void* const* d_in, const int* in_sizes, int n_in,
                              void* d_out, int out_size)
{
    const float* feats     = (const float*)d_in[0];
    const int*   word_lens = (const int*)d_in[1];
    const int*   seq_len   = (const int*)d_in[2];
    const int*   pos       = (const int*)d_in[3];
    const float* pos_table = (const float*)d_in[4];
    float* out = (float*)d_out;

    charpool_persist_kernel<<<NBLK, NT>>>(feats, word_lens, seq_len, pos, pos_table, out);
}